// round 5
// baseline (speedup 1.0000x reference)
#include <cuda_runtime.h>
#include <cstdint>

#define DIM   768
#define HOUT  64
#define ROWS  128
#define NTH   128
#define KC    32
#define NCH   24            // DIM/KC
#define XS    36            // x-chunk smem stride (words): frag banks (4g+t) all distinct
#define VS    68            // V stride (words), 64-wide rows, conflict-free

// smem: two x-chunk buffers; V (128 x VS) overlays the same region after stage 1
#define XBUF0 0
#define XBUF1 (128*XS)                    // 4608 words
#define SMEM_WORDS (2*128*XS)             // 9216 words = 36864 B  (V needs 8704 <= 9216)
#define SMEM_BYTES (SMEM_WORDS*4)

__device__ __align__(16) uint32_t g_wv[HOUT*DIM];   // tf32-rounded Wv bits
__device__ __align__(16) uint32_t g_wo[DIM*HOUT];   // tf32-rounded Wo bits

__device__ __forceinline__ uint32_t f2tf(float f) {
    uint32_t u;
    asm("cvt.rna.tf32.f32 %0, %1;" : "=r"(u) : "f"(f));
    return u;
}

__device__ __forceinline__ void mma_tf32(float* c, const uint32_t* a, uint32_t b0, uint32_t b1) {
    asm volatile(
        "mma.sync.aligned.m16n8k8.row.col.f32.tf32.tf32.f32 "
        "{%0,%1,%2,%3}, {%4,%5,%6,%7}, {%8,%9}, {%0,%1,%2,%3};\n"
        : "+f"(c[0]), "+f"(c[1]), "+f"(c[2]), "+f"(c[3])
        : "r"(a[0]), "r"(a[1]), "r"(a[2]), "r"(a[3]), "r"(b0), "r"(b1));
}

__device__ __forceinline__ void cpa16(uint32_t dst, const void* src) {
    asm volatile("cp.async.cg.shared.global [%0], [%1], 16;\n" :: "r"(dst), "l"(src));
}
#define CP_COMMIT() asm volatile("cp.async.commit_group;\n")
#define CP_WAIT0()  asm volatile("cp.async.wait_group 0;\n")

__global__ void prep_weights(const float* __restrict__ Wv, const float* __restrict__ Wo) {
    int i = blockIdx.x * blockDim.x + threadIdx.x;
    if (i < HOUT * DIM) {
        g_wv[i] = f2tf(Wv[i]);
        g_wo[i] = f2tf(Wo[i]);
    }
}

// out = (x @ Wv^T + bv) @ Wo^T + bo
// (softmax over the singleton sequence axis in the reference is identically 1,
//  so q/k/scan are mathematically dead)
__global__ void __launch_bounds__(NTH, 5)
fused_vo_kernel(const float* __restrict__ x,
                const float* __restrict__ bv,
                const float* __restrict__ bo,
                float* __restrict__ out,
                int nrows)
{
    extern __shared__ uint32_t sm[];
    uint32_t sbase;
    {
        uint64_t tmp;
        asm("cvta.to.shared.u64 %0, %1;" : "=l"(tmp) : "l"(sm));
        sbase = (uint32_t)tmp;
    }

    const int tid   = threadIdx.x;
    const int warp  = tid >> 5;
    const int lane  = tid & 31;
    const int g     = lane >> 2;
    const int t     = lane & 3;
    const int row0  = blockIdx.x * ROWS;
    const int mbase = warp * 32;        // 2 m16 tiles per warp, warp-private rows

    // x staging: 128 rows x 8 segs(16B) = 1024 segs, 8 per thread
    const int xr  = tid >> 3;           // rows xr, xr+16, ...
    const int xsg = tid & 7;

    float acc[2][8][4];
#pragma unroll
    for (int mt = 0; mt < 2; mt++)
#pragma unroll
        for (int nt = 0; nt < 8; nt++)
#pragma unroll
            for (int i = 0; i < 4; i++) acc[mt][nt][i] = 0.f;

    // ================= stage 1: V = X @ Wv^T =================
    auto issue_x = [&](int c) {
        const int xb = (c & 1) ? XBUF1 : XBUF0;
#pragma unroll
        for (int p = 0; p < 8; p++) {
            int r  = xr + p * 16;
            int gr = row0 + r; if (gr >= nrows) gr = nrows - 1;
            cpa16(sbase + (uint32_t)(xb + r * XS + xsg * 4) * 4,
                  x + (size_t)gr * DIM + c * KC + xsg * 4);
        }
        CP_COMMIT();
    };

    issue_x(0);
#pragma unroll 1
    for (int c = 0; c < NCH; c++) {
        CP_WAIT0();
        __syncthreads();                 // publishes chunk c AND proves buf (c+1)&1 readers done
        if (c < NCH - 1) issue_x(c + 1);
        const int xb = (c & 1) ? XBUF1 : XBUF0;
        const int kg = c * KC;
#pragma unroll
        for (int ks = 0; ks < 4; ks++) {
            uint32_t a[2][4];
#pragma unroll
            for (int mt = 0; mt < 2; mt++) {
                int r = mbase + mt * 16 + g;
                a[mt][0] = sm[xb + r * XS + ks * 8 + t];
                a[mt][1] = sm[xb + (r + 8) * XS + ks * 8 + t];
                a[mt][2] = sm[xb + r * XS + ks * 8 + t + 4];
                a[mt][3] = sm[xb + (r + 8) * XS + ks * 8 + t + 4];
            }
            const int k = kg + ks * 8;
#pragma unroll
            for (int nt = 0; nt < 8; nt++) {
                uint32_t b0 = __ldg(g_wv + (size_t)(nt * 8 + g) * DIM + k + t);
                uint32_t b1 = __ldg(g_wv + (size_t)(nt * 8 + g) * DIM + k + t + 4);
                mma_tf32(acc[0][nt], a[0], b0, b1);
                mma_tf32(acc[1][nt], a[1], b0, b1);
            }
        }
    }

    // V overlays the xbuf region (incl. XBUF1, read by chunk 23) -> one barrier
    __syncthreads();

    // write V (+bv), tf32-rounded; rows are warp-private so no CTA barrier after
#pragma unroll
    for (int mt = 0; mt < 2; mt++) {
#pragma unroll
        for (int nt = 0; nt < 8; nt++) {
            int col = nt * 8 + 2 * t;
            int r   = mbase + mt * 16 + g;
            float b0v = __ldg(bv + col);
            float b1v = __ldg(bv + col + 1);
            sm[r * VS + col]           = f2tf(acc[mt][nt][0] + b0v);
            sm[r * VS + col + 1]       = f2tf(acc[mt][nt][1] + b1v);
            sm[(r + 8) * VS + col]     = f2tf(acc[mt][nt][2] + b0v);
            sm[(r + 8) * VS + col + 1] = f2tf(acc[mt][nt][3] + b1v);
        }
    }
    __syncwarp();   // V readers below are the same warp's lanes only

    // ================= stage 2: OUT = V @ Wo^T (barrier-free) =================
#pragma unroll 1
    for (int c = 0; c < NCH; c++) {
        const int n0 = c * 32;

        float acc2[2][4][4];
#pragma unroll
        for (int mt = 0; mt < 2; mt++)
#pragma unroll
            for (int nt = 0; nt < 4; nt++)
#pragma unroll
                for (int i = 0; i < 4; i++) acc2[mt][nt][i] = 0.f;

#pragma unroll
        for (int ks = 0; ks < 8; ks++) {
            uint32_t a[2][4];
#pragma unroll
            for (int mt = 0; mt < 2; mt++) {
                int r = mbase + mt * 16 + g;
                a[mt][0] = sm[r * VS + ks * 8 + t];
                a[mt][1] = sm[(r + 8) * VS + ks * 8 + t];
                a[mt][2] = sm[r * VS + ks * 8 + t + 4];
                a[mt][3] = sm[(r + 8) * VS + ks * 8 + t + 4];
            }
#pragma unroll
            for (int nt = 0; nt < 4; nt++) {
                uint32_t b0 = __ldg(g_wo + (size_t)(n0 + nt * 8 + g) * HOUT + ks * 8 + t);
                uint32_t b1 = __ldg(g_wo + (size_t)(n0 + nt * 8 + g) * HOUT + ks * 8 + t + 4);
                mma_tf32(acc2[0][nt], a[0], b0, b1);
                mma_tf32(acc2[1][nt], a[1], b0, b1);
            }
        }
        // fused +bo, coalesced float2 stores
#pragma unroll
        for (int mt = 0; mt < 2; mt++) {
#pragma unroll
            for (int nt = 0; nt < 4; nt++) {
                int col = n0 + nt * 8 + 2 * t;
                float bo0 = __ldg(bo + col);
                float bo1 = __ldg(bo + col + 1);
                int r = row0 + mbase + mt * 16 + g;
                if (r < nrows) {
                    float2 o = make_float2(acc2[mt][nt][0] + bo0, acc2[mt][nt][1] + bo1);
                    *(float2*)(out + (size_t)r * DIM + col) = o;
                }
                if (r + 8 < nrows) {
                    float2 o = make_float2(acc2[mt][nt][2] + bo0, acc2[mt][nt][3] + bo1);
                    *(float2*)(out + (size_t)(r + 8) * DIM + col) = o;
                }
            }
        }
    }
}

extern "C" void kernel_launch(void* const* d_in, const int* in_sizes, int n_in,
                              void* d_out, int out_size)
{
    // metadata order: x, q_state, Wq, bq, Wk, bk, Wv, bv, Wo, bo
    const float* x  = (const float*)d_in[0];
    const float* Wv = (const float*)d_in[6];
    const float* bv = (const float*)d_in[7];
    const float* Wo = (const float*)d_in[8];
    const float* bo = (const float*)d_in[9];
    float* out = (float*)d_out;

    int nrows = in_sizes[0] / DIM;
    int grid  = (nrows + ROWS - 1) / ROWS;

    prep_weights<<<(HOUT * DIM + 255) / 256, 256>>>(Wv, Wo);

    cudaFuncSetAttribute(fused_vo_kernel,
                         cudaFuncAttributeMaxDynamicSharedMemorySize, SMEM_BYTES);
    fused_vo_kernel<<<grid, NTH, SMEM_BYTES>>>(x, bv, bo, out, nrows);
}

// round 12
// speedup vs baseline: 1.1843x; 1.1843x over previous
#include <cuda_runtime.h>
#include <cstdint>

#define DIM   768
#define HOUT  64
#define ROWS  128          // rows per CTA (32 per warp)
#define NTH   128
#define KC    32
#define NCH   24           // DIM/KC
#define XS    36           // X smem row stride (words): banks 4g+t distinct, 16B aligned
#define WXW   (2*32*XS)    // per-warp double buffer words = 2304
#define SMEM_WORDS (4*WXW) // 9216
#define SMEM_BYTES (SMEM_WORDS*4)   // 36864

// fragment-packed tf32 weights: one coalesced LDG.64 per (k-step, n-tile) per warp
__device__ __align__(16) uint2 g_wvf[96*8*32];     // [k8][nt][lane] -> {b0,b1}
__device__ __align__(16) uint2 g_wof[48*8*2*32];   // [c16][ks][nt][lane]

__device__ __forceinline__ uint32_t f2tf(float f) {
    uint32_t u;
    asm("cvt.rna.tf32.f32 %0, %1;" : "=r"(u) : "f"(f));
    return u;
}

__device__ __forceinline__ void mma_tf32(float* c, const uint32_t* a, uint32_t b0, uint32_t b1) {
    asm volatile(
        "mma.sync.aligned.m16n8k8.row.col.f32.tf32.tf32.f32 "
        "{%0,%1,%2,%3}, {%4,%5,%6,%7}, {%8,%9}, {%0,%1,%2,%3};\n"
        : "+f"(c[0]), "+f"(c[1]), "+f"(c[2]), "+f"(c[3])
        : "r"(a[0]), "r"(a[1]), "r"(a[2]), "r"(a[3]), "r"(b0), "r"(b1));
}

__device__ __forceinline__ void cpa16(uint32_t dst, const void* src) {
    asm volatile("cp.async.cg.shared.global [%0], [%1], 16;\n" :: "r"(dst), "l"(src));
}
#define CP_COMMIT() asm volatile("cp.async.commit_group;\n")
#define CP_WAIT1()  asm volatile("cp.async.wait_group 1;\n")
#define CP_WAIT0()  asm volatile("cp.async.wait_group 0;\n")

// pack Wv/Wo into MMA B-fragment lane order (tf32-rounded)
__global__ void prep_weights(const float* __restrict__ Wv, const float* __restrict__ Wo) {
    int i = blockIdx.x * blockDim.x + threadIdx.x;
    if (i >= 96*8*32) return;
    int lane = i & 31, g = lane >> 2, t = lane & 3;
    {   // g_wvf: k8 = i>>8 (0..95), nt = (i>>5)&7
        int nt = (i >> 5) & 7, k8 = i >> 8;
        int row = nt * 8 + g, k = k8 * 8 + t;
        g_wvf[i] = make_uint2(f2tf(Wv[row * DIM + k]), f2tf(Wv[row * DIM + k + 4]));
    }
    {   // g_wof: c = i>>9 (0..47), ks = (i>>6)&7, nt = (i>>5)&1
        int nt = (i >> 5) & 1, ks = (i >> 6) & 7, c = i >> 9;
        int row = c * 16 + nt * 8 + g, k = ks * 8 + t;
        g_wof[i] = make_uint2(f2tf(Wo[row * HOUT + k]), f2tf(Wo[row * HOUT + k + 4]));
    }
}

// out = (x @ Wv^T + bv) @ Wo^T + bo
// (softmax over the singleton sequence axis in the reference is identically 1,
//  so q/k/scan are mathematically dead)
// Fully barrier-free: per-warp cp.async pipelines, register-resident V via shfl.
__global__ void __launch_bounds__(NTH, 5)
fused_vo_kernel(const float* __restrict__ x,
                const float* __restrict__ bv,
                const float* __restrict__ bo,
                float* __restrict__ out,
                int nrows)
{
    extern __shared__ uint32_t sm[];
    uint32_t sbase;
    {
        uint64_t tmp;
        asm("cvta.to.shared.u64 %0, %1;" : "=l"(tmp) : "l"(sm));
        sbase = (uint32_t)tmp;
    }

    const int tid   = threadIdx.x;
    const int warp  = tid >> 5;
    const int lane  = tid & 31;
    const int g     = lane >> 2;
    const int t     = lane & 3;
    const int row0  = blockIdx.x * ROWS;
    const int wbase = warp * 32;            // warp-private 32 rows
    const int wsm   = warp * WXW;           // warp-private smem region (words)

    // per-warp X staging: 32 rows x 8 segs(16B); lane covers (rl + 4p, sg)
    const int rl = lane >> 3;               // 0..3
    const int sg = lane & 7;                // 16B segment

    float acc[2][8][4];
#pragma unroll
    for (int mt = 0; mt < 2; mt++)
#pragma unroll
        for (int nt = 0; nt < 8; nt++)
#pragma unroll
            for (int i = 0; i < 4; i++) acc[mt][nt][i] = 0.f;

    // ================= stage 1: V = X @ Wv^T (warp-autonomous) =================
    auto issue_x = [&](int c) {
        const int buf = wsm + (c & 1) * (32 * XS);
#pragma unroll
        for (int p = 0; p < 8; p++) {
            int r  = rl + p * 4;
            int gr = row0 + wbase + r; if (gr >= nrows) gr = nrows - 1;
            cpa16(sbase + (uint32_t)(buf + r * XS + sg * 4) * 4,
                  x + (size_t)gr * DIM + c * KC + sg * 4);
        }
        CP_COMMIT();
    };

    issue_x(0);
#pragma unroll 1
    for (int c = 0; c < NCH; c++) {
        if (c < NCH - 1) { issue_x(c + 1); CP_WAIT1(); }
        else             { CP_WAIT0(); }
        __syncwarp();                        // publish chunk c within the warp
        const int buf = wsm + (c & 1) * (32 * XS);
#pragma unroll
        for (int ks = 0; ks < 4; ks++) {
            uint32_t a[2][4];
#pragma unroll
            for (int mt = 0; mt < 2; mt++) {
                int r = mt * 16 + g;        // local row within warp's 32
                a[mt][0] = sm[buf + r * XS + ks * 8 + t];
                a[mt][1] = sm[buf + (r + 8) * XS + ks * 8 + t];
                a[mt][2] = sm[buf + r * XS + ks * 8 + t + 4];
                a[mt][3] = sm[buf + (r + 8) * XS + ks * 8 + t + 4];
            }
            const uint2* wp = g_wvf + ((size_t)(c * 4 + ks) * 8) * 32 + lane;
#pragma unroll
            for (int nt = 0; nt < 8; nt++) {
                uint2 b = __ldg(wp + nt * 32);
                mma_tf32(acc[0][nt], a[0], b.x, b.y);
                mma_tf32(acc[1][nt], a[1], b.x, b.y);
            }
        }
        __syncwarp();                        // readers done before buf reuse
    }

    // ======= convert V (+bv) from C-layout to stage-2 A-fragments via shfl =======
    // C-layout: lane(g,t) holds V[r][2t],V[r][2t+1] (r = mt*16+g, +8) per col-octet q.
    // A-layout needs V[r][q*8+t], V[r][q*8+t+4]: within-quad exchange.
    uint32_t af[2][8][4];
    const int s0 = (lane & 28) | (t >> 1);   // owner of col q*8 + t
    const int s1 = s0 + 2;                   // owner of col q*8 + t + 4
#pragma unroll
    for (int q = 0; q < 8; q++) {
        float bv0 = __ldg(bv + q * 8 + 2 * t);
        float bv1 = __ldg(bv + q * 8 + 2 * t + 1);
#pragma unroll
        for (int mt = 0; mt < 2; mt++) {
            float v0 = acc[mt][q][0] + bv0;
            float v1 = acc[mt][q][1] + bv1;
            float v2 = acc[mt][q][2] + bv0;
            float v3 = acc[mt][q][3] + bv1;
            float e, o;
            e = __shfl_sync(0xffffffffu, v0, s0); o = __shfl_sync(0xffffffffu, v1, s0);
            af[mt][q][0] = f2tf((t & 1) ? o : e);
            e = __shfl_sync(0xffffffffu, v2, s0); o = __shfl_sync(0xffffffffu, v3, s0);
            af[mt][q][1] = f2tf((t & 1) ? o : e);
            e = __shfl_sync(0xffffffffu, v0, s1); o = __shfl_sync(0xffffffffu, v1, s1);
            af[mt][q][2] = f2tf((t & 1) ? o : e);
            e = __shfl_sync(0xffffffffu, v2, s1); o = __shfl_sync(0xffffffffu, v3, s1);
            af[mt][q][3] = f2tf((t & 1) ? o : e);
        }
    }

    // ================= stage 2: OUT = V @ Wo^T (sync-free, smem-free) =================
#pragma unroll 1
    for (int c = 0; c < 48; c++) {           // 16 output cols per chunk
        float acc2[2][2][4];
#pragma unroll
        for (int mt = 0; mt < 2; mt++)
#pragma unroll
            for (int nt = 0; nt < 2; nt++)
#pragma unroll
                for (int i = 0; i < 4; i++) acc2[mt][nt][i] = 0.f;

        const uint2* wp = g_wof + (size_t)c * 16 * 32 + lane;
#pragma unroll
        for (int ks = 0; ks < 8; ks++) {
#pragma unroll
            for (int nt = 0; nt < 2; nt++) {
                uint2 b = __ldg(wp + (ks * 2 + nt) * 32);
                mma_tf32(acc2[0][nt], af[0][ks], b.x, b.y);
                mma_tf32(acc2[1][nt], af[1][ks], b.x, b.y);
            }
        }
#pragma unroll
        for (int mt = 0; mt < 2; mt++) {
#pragma unroll
            for (int nt = 0; nt < 2; nt++) {
                int col = c * 16 + nt * 8 + 2 * t;
                float bo0 = __ldg(bo + col);
                float bo1 = __ldg(bo + col + 1);
                int r = row0 + wbase + mt * 16 + g;
                if (r < nrows) {
                    float2 o = make_float2(acc2[mt][nt][0] + bo0, acc2[mt][nt][1] + bo1);
                    *(float2*)(out + (size_t)r * DIM + col) = o;
                }
                if (r + 8 < nrows) {
                    float2 o = make_float2(acc2[mt][nt][2] + bo0, acc2[mt][nt][3] + bo1);
                    *(float2*)(out + (size_t)(r + 8) * DIM + col) = o;
                }
            }
        }
    }
}

extern "C" void kernel_launch(void* const* d_in, const int* in_sizes, int n_in,
                              void* d_out, int out_size)
{
    // metadata order: x, q_state, Wq, bq, Wk, bk, Wv, bv, Wo, bo
    const float* x  = (const float*)d_in[0];
    const float* Wv = (const float*)d_in[6];
    const float* bv = (const float*)d_in[7];
    const float* Wo = (const float*)d_in[8];
    const float* bo = (const float*)d_in[9];
    float* out = (float*)d_out;

    int nrows = in_sizes[0] / DIM;
    int grid  = (nrows + ROWS - 1) / ROWS;

    prep_weights<<<96, 256>>>(Wv, Wo);

    cudaFuncSetAttribute(fused_vo_kernel,
                         cudaFuncAttributeMaxDynamicSharedMemorySize, SMEM_BYTES);
    fused_vo_kernel<<<grid, NTH, SMEM_BYTES>>>(x, bv, bo, out, nrows);
}

// round 15
// speedup vs baseline: 3.0960x; 2.6142x over previous
#include <cuda_runtime.h>
#include <cstdint>

#define DIM   768
#define HOUT  64
#define ROWS  128          // rows per CTA (32 per warp)
#define NTH   128
#define KC    32
#define NCH   24           // DIM/KC
#define XS    36           // X smem row stride (words): frag banks (4g+t) distinct

// smem words: two X bufs + two 8KB packed-weight bufs = 53,248 B -> 4 CTAs/SM
#define XBUF0 0
#define XBUF1 (128*XS)             // 4608
#define WBUF0 (2*128*XS)           // 9216
#define WBUF1 (WBUF0 + 2048)       // 11264
#define SMEM_WORDS (WBUF0 + 4096)  // 13312
#define SMEM_BYTES (SMEM_WORDS*4)  // 53248

// fragment-packed tf32 weights (contiguous 8KB per k/n-chunk for cp.async staging)
__device__ __align__(16) uint2 g_wvf[96*8*32];     // [k8][nt0..7][lane]
__device__ __align__(16) uint2 g_wof[24*8*4*32];   // [c32][ks][nt0..3][lane]

__device__ __forceinline__ uint32_t f2tf(float f) {
    uint32_t u;
    asm("cvt.rna.tf32.f32 %0, %1;" : "=r"(u) : "f"(f));
    return u;
}

__device__ __forceinline__ void mma_tf32(float* c, const uint32_t* a, uint32_t b0, uint32_t b1) {
    asm volatile(
        "mma.sync.aligned.m16n8k8.row.col.f32.tf32.tf32.f32 "
        "{%0,%1,%2,%3}, {%4,%5,%6,%7}, {%8,%9}, {%0,%1,%2,%3};\n"
        : "+f"(c[0]), "+f"(c[1]), "+f"(c[2]), "+f"(c[3])
        : "r"(a[0]), "r"(a[1]), "r"(a[2]), "r"(a[3]), "r"(b0), "r"(b1));
}

__device__ __forceinline__ void cpa16(uint32_t dst, const void* src) {
    asm volatile("cp.async.cg.shared.global [%0], [%1], 16;\n" :: "r"(dst), "l"(src));
}
#define CP_COMMIT() asm volatile("cp.async.commit_group;\n")
#define CP_WAIT0()  asm volatile("cp.async.wait_group 0;\n")

// pack Wv/Wo into MMA B-fragment lane order (tf32-rounded)
__global__ void prep_weights(const float* __restrict__ Wv, const float* __restrict__ Wo) {
    int i = blockIdx.x * blockDim.x + threadIdx.x;   // 0..24575
    if (i >= 96*8*32) return;
    int lane = i & 31, g = lane >> 2, t = lane & 3;
    {   // g_wvf: k8 = i>>8 (0..95), nt = (i>>5)&7
        int nt = (i >> 5) & 7, k8 = i >> 8;
        int row = nt * 8 + g, k = k8 * 8 + t;
        g_wvf[i] = make_uint2(f2tf(Wv[row * DIM + k]), f2tf(Wv[row * DIM + k + 4]));
    }
    {   // g_wof: c = i>>10 (0..23), ks = (i>>7)&7, nt = (i>>5)&3
        int nt = (i >> 5) & 3, ks = (i >> 7) & 7, c = i >> 10;
        int row = c * 32 + nt * 8 + g, k = ks * 8 + t;
        g_wof[i] = make_uint2(f2tf(Wo[row * HOUT + k]), f2tf(Wo[row * HOUT + k + 4]));
    }
}

// out = (x @ Wv^T + bv) @ Wo^T + bo
// (softmax over the singleton sequence axis in the reference is identically 1,
//  so q/k/scan are mathematically dead)
// Smem-staged packed weights (L2-latency off the critical path), one barrier
// per chunk, register-resident V via the R12-validated shfl conversion.
__global__ void __launch_bounds__(NTH, 4)
fused_vo_kernel(const float* __restrict__ x,
                const float* __restrict__ bv,
                const float* __restrict__ bo,
                float* __restrict__ out,
                int nrows)
{
    extern __shared__ uint32_t sm[];
    uint32_t sbase;
    {
        uint64_t tmp;
        asm("cvta.to.shared.u64 %0, %1;" : "=l"(tmp) : "l"(sm));
        sbase = (uint32_t)tmp;
    }

    const int tid   = threadIdx.x;
    const int warp  = tid >> 5;
    const int lane  = tid & 31;
    const int g     = lane >> 2;
    const int t     = lane & 3;
    const int row0  = blockIdx.x * ROWS;
    const int wbase = warp * 32;            // 2 m16 tiles per warp

    float acc[2][8][4];
#pragma unroll
    for (int mt = 0; mt < 2; mt++)
#pragma unroll
        for (int nt = 0; nt < 8; nt++)
#pragma unroll
            for (int i = 0; i < 4; i++) acc[mt][nt][i] = 0.f;

    // ================= stage 1: V = X @ Wv^T =================
    auto issue1 = [&](int c) {
        const int xb = (c & 1) ? XBUF1 : XBUF0;
        const int wb = (c & 1) ? WBUF1 : WBUF0;
        // X chunk: 128 rows x 8 segs(16B) = 1024 segs, 8/thread, coalesced
#pragma unroll
        for (int p = 0; p < 8; p++) {
            int f = p * NTH + tid;
            int r = f >> 3, s16 = f & 7;
            int gr = row0 + r; if (gr >= nrows) gr = nrows - 1;
            cpa16(sbase + (uint32_t)(xb + r * XS + s16 * 4) * 4,
                  x + (size_t)gr * DIM + c * KC + s16 * 4);
        }
        // packed Wv chunk: contiguous 8KB = 512 segs, 4/thread
        const char* wsrc = (const char*)g_wvf + (size_t)c * 8192;
#pragma unroll
        for (int p = 0; p < 4; p++) {
            int f = p * NTH + tid;
            cpa16(sbase + (uint32_t)(wb + f * 4) * 4, wsrc + (size_t)f * 16);
        }
        CP_COMMIT();
    };

    issue1(0);
#pragma unroll 1
    for (int c = 0; c < NCH; c++) {
        CP_WAIT0();
        __syncthreads();                 // chunk c ready AND buf (c+1)&1 readers done
        if (c < NCH - 1) issue1(c + 1);
        const int xb = (c & 1) ? XBUF1 : XBUF0;
        const uint2* wb = (const uint2*)&sm[(c & 1) ? WBUF1 : WBUF0];
#pragma unroll
        for (int ks = 0; ks < 4; ks++) {
            uint32_t a[2][4];
#pragma unroll
            for (int mt = 0; mt < 2; mt++) {
                int r = wbase + mt * 16 + g;
                a[mt][0] = sm[xb + r * XS + ks * 8 + t];
                a[mt][1] = sm[xb + (r + 8) * XS + ks * 8 + t];
                a[mt][2] = sm[xb + r * XS + ks * 8 + t + 4];
                a[mt][3] = sm[xb + (r + 8) * XS + ks * 8 + t + 4];
            }
#pragma unroll
            for (int nt = 0; nt < 8; nt++) {
                uint2 b = wb[(ks * 8 + nt) * 32 + lane];   // lane-linear LDS.64
                mma_tf32(acc[0][nt], a[0], b.x, b.y);
                mma_tf32(acc[1][nt], a[1], b.x, b.y);
            }
        }
    }

    // ================= stage 2 weight pipeline start =================
    // WBUF0 last read in compute(22); all threads passed the c=23 barrier after
    // that, so issuing into WBUF0 here is safe without another barrier.
    auto issue2 = [&](int c) {
        const int wb = (c & 1) ? WBUF1 : WBUF0;
        const char* wsrc = (const char*)g_wof + (size_t)c * 8192;
#pragma unroll
        for (int p = 0; p < 4; p++) {
            int f = p * NTH + tid;
            cpa16(sbase + (uint32_t)(wb + f * 4) * 4, wsrc + (size_t)f * 16);
        }
        CP_COMMIT();
    };
    issue2(0);

    // ======= convert V (+bv) from C-layout to stage-2 A-fragments via shfl =======
    // (numerics validated in R12: rel_err identical to the smem-V path)
    uint32_t af[2][8][4];
    const int s0 = (lane & 28) | (t >> 1);   // owner of col q*8 + t
    const int s1 = s0 + 2;                   // owner of col q*8 + t + 4
#pragma unroll
    for (int q = 0; q < 8; q++) {
        float bv0 = __ldg(bv + q * 8 + 2 * t);
        float bv1 = __ldg(bv + q * 8 + 2 * t + 1);
#pragma unroll
        for (int mt = 0; mt < 2; mt++) {
            float v0 = acc[mt][q][0] + bv0;
            float v1 = acc[mt][q][1] + bv1;
            float v2 = acc[mt][q][2] + bv0;
            float v3 = acc[mt][q][3] + bv1;
            float e, o;
            e = __shfl_sync(0xffffffffu, v0, s0); o = __shfl_sync(0xffffffffu, v1, s0);
            af[mt][q][0] = f2tf((t & 1) ? o : e);
            e = __shfl_sync(0xffffffffu, v2, s0); o = __shfl_sync(0xffffffffu, v3, s0);
            af[mt][q][1] = f2tf((t & 1) ? o : e);
            e = __shfl_sync(0xffffffffu, v0, s1); o = __shfl_sync(0xffffffffu, v1, s1);
            af[mt][q][2] = f2tf((t & 1) ? o : e);
            e = __shfl_sync(0xffffffffu, v2, s1); o = __shfl_sync(0xffffffffu, v3, s1);
            af[mt][q][3] = f2tf((t & 1) ? o : e);
        }
    }

    // ================= stage 2: OUT = V @ Wo^T =================
#pragma unroll 1
    for (int c = 0; c < NCH; c++) {          // 32 output cols per chunk
        CP_WAIT0();
        __syncthreads();
        if (c < NCH - 1) issue2(c + 1);
        const uint2* wb = (const uint2*)&sm[(c & 1) ? WBUF1 : WBUF0];

        float acc2[2][4][4];
#pragma unroll
        for (int mt = 0; mt < 2; mt++)
#pragma unroll
            for (int nt = 0; nt < 4; nt++)
#pragma unroll
                for (int i = 0; i < 4; i++) acc2[mt][nt][i] = 0.f;

#pragma unroll
        for (int ks = 0; ks < 8; ks++) {
#pragma unroll
            for (int nt = 0; nt < 4; nt++) {
                uint2 b = wb[(ks * 4 + nt) * 32 + lane];
                mma_tf32(acc2[0][nt], af[0][ks], b.x, b.y);
                mma_tf32(acc2[1][nt], af[1][ks], b.x, b.y);
            }
        }
        // fused +bo, coalesced float2 stores
        const int n0 = c * 32;
#pragma unroll
        for (int mt = 0; mt < 2; mt++) {
#pragma unroll
            for (int nt = 0; nt < 4; nt++) {
                int col = n0 + nt * 8 + 2 * t;
                float bo0 = __ldg(bo + col);
                float bo1 = __ldg(bo + col + 1);
                int r = row0 + wbase + mt * 16 + g;
                if (r < nrows) {
                    float2 o = make_float2(acc2[mt][nt][0] + bo0, acc2[mt][nt][1] + bo1);
                    *(float2*)(out + (size_t)r * DIM + col) = o;
                }
                if (r + 8 < nrows) {
                    float2 o = make_float2(acc2[mt][nt][2] + bo0, acc2[mt][nt][3] + bo1);
                    *(float2*)(out + (size_t)(r + 8) * DIM + col) = o;
                }
            }
        }
    }
}

extern "C" void kernel_launch(void* const* d_in, const int* in_sizes, int n_in,
                              void* d_out, int out_size)
{
    // metadata order: x, q_state, Wq, bq, Wk, bk, Wv, bv, Wo, bo
    const float* x  = (const float*)d_in[0];
    const float* Wv = (const float*)d_in[6];
    const float* bv = (const float*)d_in[7];
    const float* Wo = (const float*)d_in[8];
    const float* bo = (const float*)d_in[9];
    float* out = (float*)d_out;

    int nrows = in_sizes[0] / DIM;
    int grid  = (nrows + ROWS - 1) / ROWS;

    prep_weights<<<96, 256>>>(Wv, Wo);

    cudaFuncSetAttribute(fused_vo_kernel,
                         cudaFuncAttributeMaxDynamicSharedMemorySize, SMEM_BYTES);
    fused_vo_kernel<<<grid, NTH, SMEM_BYTES>>>(x, bv, bo, out, nrows);
}